// round 9
// baseline (speedup 1.0000x reference)
#include <cuda_runtime.h>
#include <cuda_bf16.h>
#include <cuda_fp8.h>
#include <cstdint>
#include <cstddef>

// ---------------------------------------------------------------------------
// Problem constants.  ALL in/out buffers are FLOAT32 carriers of bf16 values.
// ---------------------------------------------------------------------------
#define NROWS 32768
#define KDIM  2048
#define ODIM  2048

// GEMM tiling: 128x256 CTA tile, KC=128 (16 barriers), warp tile 64x64.
#define TM 128
#define TN 256
#define KC 128
#define STAGES 2
#define NCHUNK (KDIM / KC)      // 16
#define THREADS 256             // 8 warps: 2 (M) x 4 (N)

// Padded-linear smem rows: 256B data + 16B pad -> conflict-free ldsm & STS
#define RS 272
#define STAGE_A_BYTES (TM * RS)                         // 34816
#define STAGE_B_BYTES (TN * RS)                         // 69632
#define STAGE_BYTES   (STAGE_A_BYTES + STAGE_B_BYTES)   // 104448
#define SMEM_DYN      (STAGES * STAGE_BYTES)            // 208896

// bf16 scratch: quantized x (134MB) and converted W (8MB)
__device__ __nv_bfloat16 g_xq[(size_t)NROWS * KDIM];
__device__ __nv_bfloat16 g_wb[(size_t)ODIM * KDIM];

// ---------------------------------------------------------------------------
// helpers
// ---------------------------------------------------------------------------
__device__ __forceinline__ uint32_t smem_u32(const void* p) {
    uint32_t a;
    asm("{ .reg .u64 t; cvta.to.shared.u64 t, %1; cvt.u32.u64 %0, t; }"
        : "=r"(a) : "l"(p));
    return a;
}

__device__ __forceinline__ void cp16(uint32_t dst_smem, const void* src) {
    asm volatile("cp.async.cg.shared.global [%0], [%1], 16;"
                 :: "r"(dst_smem), "l"(__cvta_generic_to_global(src)) : "memory");
}

__device__ __forceinline__ void ldsm4(uint32_t (&r)[4], uint32_t addr) {
    asm volatile("ldmatrix.sync.aligned.m8n8.x4.shared.b16 {%0,%1,%2,%3}, [%4];"
                 : "=r"(r[0]), "=r"(r[1]), "=r"(r[2]), "=r"(r[3]) : "r"(addr));
}

__device__ __forceinline__ void mma16816(float (&d)[4], const uint32_t (&a)[4],
                                         uint32_t b0, uint32_t b1) {
    asm volatile(
        "mma.sync.aligned.m16n8k16.row.col.f32.bf16.bf16.f32 "
        "{%0,%1,%2,%3}, {%4,%5,%6,%7}, {%8,%9}, {%0,%1,%2,%3};"
        : "+f"(d[0]), "+f"(d[1]), "+f"(d[2]), "+f"(d[3])
        : "r"(a[0]), "r"(a[1]), "r"(a[2]), "r"(a[3]), "r"(b0), "r"(b1));
}

// ---------------------------------------------------------------------------
// Kernel 1: quantize-dequant f32 x -> bf16 g_xq (reference-exact chain)
// ---------------------------------------------------------------------------
__global__ void __launch_bounds__(256) quant_kernel(const float4* __restrict__ x,
                                                    const float* __restrict__ scale,
                                                    uint2* __restrict__ xq, long n4) {
    __nv_bfloat16 sb = __float2bfloat16(scale[0]);
    float sbf = __bfloat162float(sb);
    long i = (long)blockIdx.x * blockDim.x + threadIdx.x;
    long stride = (long)gridDim.x * blockDim.x;
    for (; i < n4; i += stride) {
        float4 v = x[i];
        __nv_bfloat16 o[4];
        float in[4] = {v.x, v.y, v.z, v.w};
#pragma unroll
        for (int e = 0; e < 4; e++) {
            float xb = __bfloat162float(__float2bfloat16(in[e]));
            float xs = __bfloat162float(__float2bfloat16(xb / sbf));
            __nv_fp8_storage_t q = __nv_cvt_float_to_fp8(xs, __NV_SATFINITE, __NV_E4M3);
            __half_raw hr = __nv_cvt_fp8_to_halfraw(q, __NV_E4M3);
            o[e] = __hmul(__float2bfloat16(__half2float(__half(hr))), sb);
        }
        __nv_bfloat162 p0 = __halves2bfloat162(o[0], o[1]);
        __nv_bfloat162 p1 = __halves2bfloat162(o[2], o[3]);
        xq[i] = make_uint2(*reinterpret_cast<uint32_t*>(&p0),
                           *reinterpret_cast<uint32_t*>(&p1));
    }
}

// Kernel 1b: W f32 -> bf16
__global__ void __launch_bounds__(256) wconv_kernel(const float4* __restrict__ w,
                                                    uint2* __restrict__ wb, long n4) {
    long i = (long)blockIdx.x * blockDim.x + threadIdx.x;
    long stride = (long)gridDim.x * blockDim.x;
    for (; i < n4; i += stride) {
        float4 v = w[i];
        __nv_bfloat162 p0 = __halves2bfloat162(__float2bfloat16(v.x),
                                               __float2bfloat16(v.y));
        __nv_bfloat162 p1 = __halves2bfloat162(__float2bfloat16(v.z),
                                               __float2bfloat16(v.w));
        wb[i] = make_uint2(*reinterpret_cast<uint32_t*>(&p0),
                           *reinterpret_cast<uint32_t*>(&p1));
    }
}

// ---------------------------------------------------------------------------
// Kernel 2: GEMM  out[m,o] = f32( bf16(sum_k xq[m,k]*wb[o,k]) +bf16 bias[o] )
// KC=128 chunks (16 barriers), fragment double-buffer across k-steps.
// ---------------------------------------------------------------------------
__device__ __forceinline__ void load_chunk(uint32_t st, const __nv_bfloat16* A,
                                           const __nv_bfloat16* W,
                                           int m0, int n0, int k0, int tid) {
    // A: 128 rows x 16 16B-units = 2048 units, 8 per thread
#pragma unroll
    for (int t = 0; t < 8; t++) {
        int u = tid + t * THREADS;
        int row = u >> 4, c = u & 15;
        cp16(st + (uint32_t)(row * RS + c * 16),
             A + (size_t)(m0 + row) * KDIM + (size_t)(k0 + c * 8));
    }
    // B: 256 rows x 16 units = 4096 units, 16 per thread
#pragma unroll
    for (int t = 0; t < 16; t++) {
        int u = tid + t * THREADS;
        int row = u >> 4, c = u & 15;
        cp16(st + STAGE_A_BYTES + (uint32_t)(row * RS + c * 16),
             W + (size_t)(n0 + row) * KDIM + (size_t)(k0 + c * 8));
    }
}

__global__ void __launch_bounds__(THREADS, 1) gemm_kernel(
    const __nv_bfloat16* __restrict__ A,
    const __nv_bfloat16* __restrict__ W,
    const float* __restrict__ bias,
    float* __restrict__ out) {
    extern __shared__ __align__(128) char smem_raw[];
    const uint32_t sbase = smem_u32(smem_raw);

    const int tid = threadIdx.x;
    const int wid = tid >> 5, lane = tid & 31;
    const int wm = wid >> 2;         // 0..1  (M warp, 64 rows)
    const int wn = wid & 3;          // 0..3  (N warp, 64 cols)
    const int n0 = (int)(blockIdx.x & 7) * TN;   // N fastest: xq-tile L2 reuse
    const int m0 = (int)(blockIdx.x >> 3) * TM;

    const int lrow = lane & 15;
    const int lhalf = lane >> 4;
    const uint32_t abase = (uint32_t)((wm * 64 + lrow) * RS + lhalf * 16);
    const uint32_t bbase = (uint32_t)((wn * 64 + lrow) * RS + lhalf * 16);

    float acc[4][8][4];
#pragma unroll
    for (int i = 0; i < 4; i++)
#pragma unroll
        for (int j = 0; j < 8; j++)
#pragma unroll
            for (int e = 0; e < 4; e++) acc[i][j][e] = 0.0f;

    // Prologue: chunk 0 in flight.
    load_chunk(sbase + 0 * STAGE_BYTES, A, W, m0, n0, 0, tid);
    asm volatile("cp.async.commit_group;" ::: "memory");

    uint32_t a[2][4][4], b[2][4][4];   // fragment double buffer (ks parity)

    for (int i = 0; i < NCHUNK; i++) {
        asm volatile("cp.async.wait_group 0;" ::: "memory");
        __syncthreads();   // chunk i resident; other stage free

        const uint32_t stA = sbase + (uint32_t)(i & 1) * STAGE_BYTES;
        const uint32_t stB = stA + STAGE_A_BYTES;

        // Prefetch ks=0 fragments BEFORE burning issue slots on cp.async.
#pragma unroll
        for (int mf = 0; mf < 4; mf++)
            ldsm4(a[0][mf], stA + abase + (uint32_t)(mf * 16 * RS));
#pragma unroll
        for (int nt = 0; nt < 4; nt++)
            ldsm4(b[0][nt], stB + bbase + (uint32_t)(nt * 16 * RS));

        if (i + 1 < NCHUNK) {
            load_chunk(sbase + (uint32_t)((i + 1) & 1) * STAGE_BYTES, A, W,
                       m0, n0, (i + 1) * KC, tid);
            asm volatile("cp.async.commit_group;" ::: "memory");
        }

#pragma unroll
        for (int ks = 0; ks < 8; ks++) {
            const int cur = ks & 1, nxt = cur ^ 1;
            if (ks < 7) {   // load ks+1 fragments while ks HMMAs drain
                uint32_t xoff = (uint32_t)((ks + 1) * 32);
#pragma unroll
                for (int mf = 0; mf < 4; mf++)
                    ldsm4(a[nxt][mf], stA + abase + (uint32_t)(mf * 16 * RS) + xoff);
#pragma unroll
                for (int nt = 0; nt < 4; nt++)
                    ldsm4(b[nxt][nt], stB + bbase + (uint32_t)(nt * 16 * RS) + xoff);
            }
#pragma unroll
            for (int mf = 0; mf < 4; mf++)
#pragma unroll
                for (int nt = 0; nt < 4; nt++) {
                    mma16816(acc[mf][2 * nt + 0], a[cur][mf], b[cur][nt][0], b[cur][nt][2]);
                    mma16816(acc[mf][2 * nt + 1], a[cur][mf], b[cur][nt][1], b[cur][nt][3]);
                }
        }
    }

    // Epilogue: f32 acc -> bf16, +bf16 bias, upconvert to f32 store.
    const int qrow = lane >> 2;
    const int qcol = (lane & 3) * 2;
#pragma unroll
    for (int mf = 0; mf < 4; mf++) {
#pragma unroll
        for (int nf = 0; nf < 8; nf++) {
            int col = n0 + wn * 64 + nf * 8 + qcol;
            __nv_bfloat16 b0 = __float2bfloat16(bias[col]);
            __nv_bfloat16 b1 = __float2bfloat16(bias[col + 1]);
            size_t r0 = (size_t)(m0 + wm * 64 + mf * 16 + qrow);
            float2 v0 = make_float2(
                __bfloat162float(__hadd(__float2bfloat16(acc[mf][nf][0]), b0)),
                __bfloat162float(__hadd(__float2bfloat16(acc[mf][nf][1]), b1)));
            float2 v1 = make_float2(
                __bfloat162float(__hadd(__float2bfloat16(acc[mf][nf][2]), b0)),
                __bfloat162float(__hadd(__float2bfloat16(acc[mf][nf][3]), b1)));
            *reinterpret_cast<float2*>(out + r0 * ODIM + col) = v0;
            *reinterpret_cast<float2*>(out + (r0 + 8) * ODIM + col) = v1;
        }
    }
}

// ---------------------------------------------------------------------------
// kernel_launch — inputs identified BY SIZE; all buffers FLOAT32
// ---------------------------------------------------------------------------
extern "C" void kernel_launch(void* const* d_in, const int* in_sizes, int n_in,
                              void* d_out, int out_size) {
    const float* x    = nullptr;
    const float* w    = nullptr;
    const float* bias = nullptr;
    const float* scale = nullptr;
    for (int i = 0; i < n_in; i++) {
        long s = (long)in_sizes[i];
        if (s == (long)NROWS * KDIM)      x     = (const float*)d_in[i];
        else if (s == (long)ODIM * KDIM)  w     = (const float*)d_in[i];
        else if (s == (long)ODIM)         bias  = (const float*)d_in[i];
        else if (s == 1)                  scale = (const float*)d_in[i];
    }
    float* out = (float*)d_out;

    void* xq_ptr = nullptr;
    void* wb_ptr = nullptr;
    cudaGetSymbolAddress(&xq_ptr, g_xq);
    cudaGetSymbolAddress(&wb_ptr, g_wb);

    quant_kernel<<<4096, 256>>>((const float4*)x, scale, (uint2*)xq_ptr,
                                (long)NROWS * KDIM / 4);
    wconv_kernel<<<1024, 256>>>((const float4*)w, (uint2*)wb_ptr,
                                (long)ODIM * KDIM / 4);

    cudaFuncSetAttribute(gemm_kernel, cudaFuncAttributeMaxDynamicSharedMemorySize,
                         SMEM_DYN);
    gemm_kernel<<<(NROWS / TM) * (ODIM / TN), THREADS, SMEM_DYN>>>(
        (const __nv_bfloat16*)xq_ptr, (const __nv_bfloat16*)wb_ptr, bias, out);
}

// round 10
// speedup vs baseline: 1.0253x; 1.0253x over previous
#include <cuda_runtime.h>
#include <cuda_bf16.h>
#include <cuda_fp8.h>
#include <cstdint>
#include <cstddef>

// ---------------------------------------------------------------------------
// Problem constants.  ALL in/out buffers are FLOAT32 carriers of bf16 values.
// ---------------------------------------------------------------------------
#define NROWS 32768
#define KDIM  2048
#define ODIM  2048

// GEMM tiling: 128x128 CTA tile, 256 threads, 2 CTAs/SM (4 warps/SMSP).
// Measured best (r8): legacy mma.sync throughput ceiling ~300 TF/s.
#define TM 128
#define TN 128
#define KC 64
#define STAGES 3
#define NCHUNK (KDIM / KC)      // 32
#define THREADS 256             // 8 warps: 2 (M) x 4 (N), warp tile 64x32

#define RS 144
#define STAGE_A_BYTES (TM * RS)                         // 18432
#define STAGE_B_BYTES (TN * RS)                         // 18432
#define STAGE_BYTES   (STAGE_A_BYTES + STAGE_B_BYTES)   // 36864
#define SMEM_DYN      (STAGES * STAGE_BYTES)            // 110592 (x2 CTAs = 216KB)

// bf16 scratch: quantized x (134MB) and converted W (8MB)
__device__ __nv_bfloat16 g_xq[(size_t)NROWS * KDIM];
__device__ __nv_bfloat16 g_wb[(size_t)ODIM * KDIM];

#define XUNITS ((long)NROWS * KDIM / 8)   // 8388608 8-f32 units
#define WUNITS ((long)ODIM * KDIM / 8)    // 524288
#define TUNITS (XUNITS + WUNITS)

// ---------------------------------------------------------------------------
// helpers
// ---------------------------------------------------------------------------
__device__ __forceinline__ uint32_t smem_u32(const void* p) {
    uint32_t a;
    asm("{ .reg .u64 t; cvta.to.shared.u64 t, %1; cvt.u32.u64 %0, t; }"
        : "=r"(a) : "l"(p));
    return a;
}

__device__ __forceinline__ void cp16(uint32_t dst_smem, const void* src) {
    asm volatile("cp.async.cg.shared.global [%0], [%1], 16;"
                 :: "r"(dst_smem), "l"(__cvta_generic_to_global(src)) : "memory");
}

__device__ __forceinline__ void ldsm4(uint32_t (&r)[4], uint32_t addr) {
    asm volatile("ldmatrix.sync.aligned.m8n8.x4.shared.b16 {%0,%1,%2,%3}, [%4];"
                 : "=r"(r[0]), "=r"(r[1]), "=r"(r[2]), "=r"(r[3]) : "r"(addr));
}

__device__ __forceinline__ void mma16816(float (&d)[4], const uint32_t (&a)[4],
                                         uint32_t b0, uint32_t b1) {
    asm volatile(
        "mma.sync.aligned.m16n8k16.row.col.f32.bf16.bf16.f32 "
        "{%0,%1,%2,%3}, {%4,%5,%6,%7}, {%8,%9}, {%0,%1,%2,%3};"
        : "+f"(d[0]), "+f"(d[1]), "+f"(d[2]), "+f"(d[3])
        : "r"(a[0]), "r"(a[1]), "r"(a[2]), "r"(a[3]), "r"(b0), "r"(b1));
}

// Packed bf16x2 from two floats (rounds both)
__device__ __forceinline__ uint32_t bf16x2_f32(float lo, float hi) {
    uint32_t r;
    asm("cvt.rn.bf16x2.f32 %0, %1, %2;" : "=r"(r) : "f"(hi), "f"(lo));
    return r;
}

// Fast quant of 2 elements (scale == 1.0): f32 -> e4m3(satfinite) -> bf16x2.
// Exact match of reference chain when scale == 1 (all converts exact except
// the single e4m3 rounding, identical to reference).
__device__ __forceinline__ uint32_t qdq2_s1(float lo, float hi) {
    uint16_t p8;
    asm("cvt.rn.satfinite.e4m3x2.f32 %0, %1, %2;" : "=h"(p8) : "f"(hi), "f"(lo));
    uint32_t h2;
    asm("cvt.rn.f16x2.e4m3x2 %0, %1;" : "=r"(h2) : "h"(p8));
    __half2 h = *reinterpret_cast<__half2*>(&h2);
    return bf16x2_f32(__half2float(__low2half(h)), __half2float(__high2half(h)));
}

// Exact general-scale chain (reference-faithful, with f32 divide)
__device__ __forceinline__ __nv_bfloat16 qdq_gen(float v, float sbf, __nv_bfloat16 sb) {
    float xb = __bfloat162float(__float2bfloat16(v));
    float xs = __bfloat162float(__float2bfloat16(xb / sbf));
    __nv_fp8_storage_t q = __nv_cvt_float_to_fp8(xs, __NV_SATFINITE, __NV_E4M3);
    __half_raw hr = __nv_cvt_fp8_to_halfraw(q, __NV_E4M3);
    return __hmul(__float2bfloat16(__half2float(__half(hr))), sb);
}

// ---------------------------------------------------------------------------
// Kernel 1: merged prepass. Units of 8 f32 (32B in, 16B out).
//   unit < XUNITS: quantize-dequant x -> g_xq
//   else:          convert w -> g_wb
// ---------------------------------------------------------------------------
__global__ void __launch_bounds__(256) prep_kernel(const float4* __restrict__ x,
                                                   const float4* __restrict__ w,
                                                   const float* __restrict__ scale,
                                                   uint4* __restrict__ xq,
                                                   uint4* __restrict__ wb) {
    const __nv_bfloat16 sb = __float2bfloat16(scale[0]);
    const float sbf = __bfloat162float(sb);
    const bool s1 = (sbf == 1.0f);
    long i = (long)blockIdx.x * blockDim.x + threadIdx.x;
    const long stride = (long)gridDim.x * blockDim.x;
    for (; i < TUNITS; i += stride) {
        if (i < XUNITS) {
            float4 v0 = x[2 * i], v1 = x[2 * i + 1];
            uint4 o;
            if (s1) {
                o.x = qdq2_s1(v0.x, v0.y);
                o.y = qdq2_s1(v0.z, v0.w);
                o.z = qdq2_s1(v1.x, v1.y);
                o.w = qdq2_s1(v1.z, v1.w);
            } else {
                __nv_bfloat162 p0 = __halves2bfloat162(qdq_gen(v0.x, sbf, sb),
                                                       qdq_gen(v0.y, sbf, sb));
                __nv_bfloat162 p1 = __halves2bfloat162(qdq_gen(v0.z, sbf, sb),
                                                       qdq_gen(v0.w, sbf, sb));
                __nv_bfloat162 p2 = __halves2bfloat162(qdq_gen(v1.x, sbf, sb),
                                                       qdq_gen(v1.y, sbf, sb));
                __nv_bfloat162 p3 = __halves2bfloat162(qdq_gen(v1.z, sbf, sb),
                                                       qdq_gen(v1.w, sbf, sb));
                o.x = *reinterpret_cast<uint32_t*>(&p0);
                o.y = *reinterpret_cast<uint32_t*>(&p1);
                o.z = *reinterpret_cast<uint32_t*>(&p2);
                o.w = *reinterpret_cast<uint32_t*>(&p3);
            }
            xq[i] = o;
        } else {
            long j = i - XUNITS;
            float4 v0 = w[2 * j], v1 = w[2 * j + 1];
            uint4 o;
            o.x = bf16x2_f32(v0.x, v0.y);
            o.y = bf16x2_f32(v0.z, v0.w);
            o.z = bf16x2_f32(v1.x, v1.y);
            o.w = bf16x2_f32(v1.z, v1.w);
            wb[j] = o;
        }
    }
}

// ---------------------------------------------------------------------------
// Kernel 2: GEMM  out[m,o] = f32( bf16(sum_k xq[m,k]*wb[o,k]) +bf16 bias[o] )
// r8 config verbatim (measured best: 919us GEMM).
// ---------------------------------------------------------------------------
__device__ __forceinline__ void load_chunk(uint32_t st, const __nv_bfloat16* A,
                                           const __nv_bfloat16* W,
                                           int m0, int n0, int k0, int tid) {
#pragma unroll
    for (int t = 0; t < 4; t++) {
        int u = tid + t * THREADS;
        int row = u >> 3, c = u & 7;
        cp16(st + (uint32_t)(row * RS + c * 16),
             A + (size_t)(m0 + row) * KDIM + (size_t)(k0 + c * 8));
    }
#pragma unroll
    for (int t = 0; t < 4; t++) {
        int u = tid + t * THREADS;
        int row = u >> 3, c = u & 7;
        cp16(st + STAGE_A_BYTES + (uint32_t)(row * RS + c * 16),
             W + (size_t)(n0 + row) * KDIM + (size_t)(k0 + c * 8));
    }
}

__global__ void __launch_bounds__(THREADS, 2) gemm_kernel(
    const __nv_bfloat16* __restrict__ A,
    const __nv_bfloat16* __restrict__ W,
    const float* __restrict__ bias,
    float* __restrict__ out) {
    extern __shared__ __align__(128) char smem_raw[];
    const uint32_t sbase = smem_u32(smem_raw);

    const int tid = threadIdx.x;
    const int wid = tid >> 5, lane = tid & 31;
    const int wm = wid >> 2;
    const int wn = wid & 3;
    const int n0 = (int)(blockIdx.x & 15) * TN;
    const int m0 = (int)(blockIdx.x >> 4) * TM;

    const int lrow = lane & 15;
    const int lhalf = lane >> 4;
    const uint32_t abase = (uint32_t)((wm * 64 + lrow) * RS + lhalf * 16);
    const uint32_t bbase = (uint32_t)((wn * 32 + lrow) * RS + lhalf * 16);

    float acc[4][4][4];
#pragma unroll
    for (int i = 0; i < 4; i++)
#pragma unroll
        for (int j = 0; j < 4; j++)
#pragma unroll
            for (int e = 0; e < 4; e++) acc[i][j][e] = 0.0f;

    load_chunk(sbase + 0 * STAGE_BYTES, A, W, m0, n0, 0 * KC, tid);
    asm volatile("cp.async.commit_group;" ::: "memory");
    load_chunk(sbase + 1 * STAGE_BYTES, A, W, m0, n0, 1 * KC, tid);
    asm volatile("cp.async.commit_group;" ::: "memory");

    for (int i = 0; i < NCHUNK; i++) {
        if (i < NCHUNK - 1) asm volatile("cp.async.wait_group 1;" ::: "memory");
        else                asm volatile("cp.async.wait_group 0;" ::: "memory");
        __syncthreads();

        if (i + 2 < NCHUNK) {
            load_chunk(sbase + ((i + 2) % STAGES) * STAGE_BYTES, A, W,
                       m0, n0, (i + 2) * KC, tid);
            asm volatile("cp.async.commit_group;" ::: "memory");
        }

        const uint32_t stA = sbase + (i % STAGES) * STAGE_BYTES;
        const uint32_t stB = stA + STAGE_A_BYTES;
#pragma unroll
        for (int ks = 0; ks < 4; ks++) {
            uint32_t a[4][4], b[2][4];
#pragma unroll
            for (int mf = 0; mf < 4; mf++)
                ldsm4(a[mf], stA + abase + (uint32_t)(mf * 16 * RS + ks * 32));
#pragma unroll
            for (int nt = 0; nt < 2; nt++)
                ldsm4(b[nt], stB + bbase + (uint32_t)(nt * 16 * RS + ks * 32));
#pragma unroll
            for (int mf = 0; mf < 4; mf++)
#pragma unroll
                for (int nt = 0; nt < 2; nt++) {
                    mma16816(acc[mf][2 * nt + 0], a[mf], b[nt][0], b[nt][2]);
                    mma16816(acc[mf][2 * nt + 1], a[mf], b[nt][1], b[nt][3]);
                }
        }
    }

    const int qrow = lane >> 2;
    const int qcol = (lane & 3) * 2;
#pragma unroll
    for (int mf = 0; mf < 4; mf++) {
#pragma unroll
        for (int nf = 0; nf < 4; nf++) {
            int col = n0 + wn * 32 + nf * 8 + qcol;
            __nv_bfloat16 b0 = __float2bfloat16(bias[col]);
            __nv_bfloat16 b1 = __float2bfloat16(bias[col + 1]);
            size_t r0 = (size_t)(m0 + wm * 64 + mf * 16 + qrow);
            float2 v0 = make_float2(
                __bfloat162float(__hadd(__float2bfloat16(acc[mf][nf][0]), b0)),
                __bfloat162float(__hadd(__float2bfloat16(acc[mf][nf][1]), b1)));
            float2 v1 = make_float2(
                __bfloat162float(__hadd(__float2bfloat16(acc[mf][nf][2]), b0)),
                __bfloat162float(__hadd(__float2bfloat16(acc[mf][nf][3]), b1)));
            *reinterpret_cast<float2*>(out + r0 * ODIM + col) = v0;
            *reinterpret_cast<float2*>(out + (r0 + 8) * ODIM + col) = v1;
        }
    }
}

// ---------------------------------------------------------------------------
// kernel_launch — inputs identified BY SIZE; all buffers FLOAT32
// ---------------------------------------------------------------------------
extern "C" void kernel_launch(void* const* d_in, const int* in_sizes, int n_in,
                              void* d_out, int out_size) {
    const float* x    = nullptr;
    const float* w    = nullptr;
    const float* bias = nullptr;
    const float* scale = nullptr;
    for (int i = 0; i < n_in; i++) {
        long s = (long)in_sizes[i];
        if (s == (long)NROWS * KDIM)      x     = (const float*)d_in[i];
        else if (s == (long)ODIM * KDIM)  w     = (const float*)d_in[i];
        else if (s == (long)ODIM)         bias  = (const float*)d_in[i];
        else if (s == 1)                  scale = (const float*)d_in[i];
    }
    float* out = (float*)d_out;

    void* xq_ptr = nullptr;
    void* wb_ptr = nullptr;
    cudaGetSymbolAddress(&xq_ptr, g_xq);
    cudaGetSymbolAddress(&wb_ptr, g_wb);

    prep_kernel<<<4096, 256>>>((const float4*)x, (const float4*)w, scale,
                               (uint4*)xq_ptr, (uint4*)wb_ptr);

    cudaFuncSetAttribute(gemm_kernel, cudaFuncAttributeMaxDynamicSharedMemorySize,
                         SMEM_DYN);
    gemm_kernel<<<(NROWS / TM) * (ODIM / TN), THREADS, SMEM_DYN>>>(
        (const __nv_bfloat16*)xq_ptr, (const __nv_bfloat16*)wb_ptr, bias, out);
}

// round 11
// speedup vs baseline: 1.0767x; 1.0501x over previous
#include <cuda_runtime.h>
#include <cuda_bf16.h>
#include <cuda_fp8.h>
#include <cstdint>
#include <cstddef>

// ---------------------------------------------------------------------------
// Problem constants.  ALL in/out buffers are FLOAT32 carriers of bf16 values.
// ---------------------------------------------------------------------------
#define NROWS 32768
#define KDIM  2048
#define ODIM  2048

// GEMM tiling: 128x128 CTA tile, 256 threads, 2 CTAs/SM (4 warps/SMSP).
#define TM 128
#define TN 128
#define KC 64
#define STAGES 3
#define NCHUNK (KDIM / KC)      // 32
#define THREADS 256             // 8 warps: 2 (M) x 4 (N), warp tile 64x32

#define RS 144
#define STAGE_A_BYTES (TM * RS)                         // 18432
#define STAGE_B_BYTES (TN * RS)                         // 18432
#define STAGE_BYTES   (STAGE_A_BYTES + STAGE_B_BYTES)   // 36864
#define SMEM_DYN      (STAGES * STAGE_BYTES)            // 110592 (x2 CTAs = 216KB)

// bf16 scratch: quantized x (134MB) and converted W (8MB)
__device__ __nv_bfloat16 g_xq[(size_t)NROWS * KDIM];
__device__ __nv_bfloat16 g_wb[(size_t)ODIM * KDIM];

#define XUNITS ((long)NROWS * KDIM / 8)   // 8388608 8-f32 units
#define WUNITS ((long)ODIM * KDIM / 8)    // 524288
#define TUNITS (XUNITS + WUNITS)

// ---------------------------------------------------------------------------
// helpers
// ---------------------------------------------------------------------------
__device__ __forceinline__ uint32_t smem_u32(const void* p) {
    uint32_t a;
    asm("{ .reg .u64 t; cvta.to.shared.u64 t, %1; cvt.u32.u64 %0, t; }"
        : "=r"(a) : "l"(p));
    return a;
}

__device__ __forceinline__ void cp16(uint32_t dst_smem, const void* src) {
    asm volatile("cp.async.cg.shared.global [%0], [%1], 16;"
                 :: "r"(dst_smem), "l"(__cvta_generic_to_global(src)) : "memory");
}

__device__ __forceinline__ void ldsm4(uint32_t (&r)[4], uint32_t addr) {
    asm volatile("ldmatrix.sync.aligned.m8n8.x4.shared.b16 {%0,%1,%2,%3}, [%4];"
                 : "=r"(r[0]), "=r"(r[1]), "=r"(r[2]), "=r"(r[3]) : "r"(addr));
}

__device__ __forceinline__ void mma16816(float (&d)[4], const uint32_t (&a)[4],
                                         uint32_t b0, uint32_t b1) {
    asm volatile(
        "mma.sync.aligned.m16n8k16.row.col.f32.bf16.bf16.f32 "
        "{%0,%1,%2,%3}, {%4,%5,%6,%7}, {%8,%9}, {%0,%1,%2,%3};"
        : "+f"(d[0]), "+f"(d[1]), "+f"(d[2]), "+f"(d[3])
        : "r"(a[0]), "r"(a[1]), "r"(a[2]), "r"(a[3]), "r"(b0), "r"(b1));
}

// Packed bf16x2 from two floats
__device__ __forceinline__ uint32_t bf16x2_f32(float lo, float hi) {
    uint32_t r;
    asm("cvt.rn.bf16x2.f32 %0, %1, %2;" : "=r"(r) : "f"(hi), "f"(lo));
    return r;
}

// Fast quant of 2 elements (scale == 1.0): f32 -> e4m3(satfinite) -> bf16x2.
__device__ __forceinline__ uint32_t qdq2_s1(float lo, float hi) {
    uint16_t p8;
    asm("cvt.rn.satfinite.e4m3x2.f32 %0, %1, %2;" : "=h"(p8) : "f"(hi), "f"(lo));
    uint32_t h2;
    asm("cvt.rn.f16x2.e4m3x2 %0, %1;" : "=r"(h2) : "h"(p8));
    __half2 h = *reinterpret_cast<__half2*>(&h2);
    return bf16x2_f32(__half2float(__low2half(h)), __half2float(__high2half(h)));
}

// Exact general-scale chain (reference-faithful)
__device__ __forceinline__ __nv_bfloat16 qdq_gen(float v, float sbf, __nv_bfloat16 sb) {
    float xb = __bfloat162float(__float2bfloat16(v));
    float xs = __bfloat162float(__float2bfloat16(xb / sbf));
    __nv_fp8_storage_t q = __nv_cvt_float_to_fp8(xs, __NV_SATFINITE, __NV_E4M3);
    __half_raw hr = __nv_cvt_fp8_to_halfraw(q, __NV_E4M3);
    return __hmul(__float2bfloat16(__half2float(__half(hr))), sb);
}

// ---------------------------------------------------------------------------
// Kernel 1: merged prepass (x quant + W convert), units of 8 f32.
// ---------------------------------------------------------------------------
__global__ void __launch_bounds__(256) prep_kernel(const float4* __restrict__ x,
                                                   const float4* __restrict__ w,
                                                   const float* __restrict__ scale,
                                                   uint4* __restrict__ xq,
                                                   uint4* __restrict__ wb) {
    const __nv_bfloat16 sb = __float2bfloat16(scale[0]);
    const float sbf = __bfloat162float(sb);
    const bool s1 = (sbf == 1.0f);
    long i = (long)blockIdx.x * blockDim.x + threadIdx.x;
    const long stride = (long)gridDim.x * blockDim.x;
    for (; i < TUNITS; i += stride) {
        if (i < XUNITS) {
            float4 v0 = x[2 * i], v1 = x[2 * i + 1];
            uint4 o;
            if (s1) {
                o.x = qdq2_s1(v0.x, v0.y);
                o.y = qdq2_s1(v0.z, v0.w);
                o.z = qdq2_s1(v1.x, v1.y);
                o.w = qdq2_s1(v1.z, v1.w);
            } else {
                __nv_bfloat162 p0 = __halves2bfloat162(qdq_gen(v0.x, sbf, sb),
                                                       qdq_gen(v0.y, sbf, sb));
                __nv_bfloat162 p1 = __halves2bfloat162(qdq_gen(v0.z, sbf, sb),
                                                       qdq_gen(v0.w, sbf, sb));
                __nv_bfloat162 p2 = __halves2bfloat162(qdq_gen(v1.x, sbf, sb),
                                                       qdq_gen(v1.y, sbf, sb));
                __nv_bfloat162 p3 = __halves2bfloat162(qdq_gen(v1.z, sbf, sb),
                                                       qdq_gen(v1.w, sbf, sb));
                o.x = *reinterpret_cast<uint32_t*>(&p0);
                o.y = *reinterpret_cast<uint32_t*>(&p1);
                o.z = *reinterpret_cast<uint32_t*>(&p2);
                o.w = *reinterpret_cast<uint32_t*>(&p3);
            }
            xq[i] = o;
        } else {
            long j = i - XUNITS;
            float4 v0 = w[2 * j], v1 = w[2 * j + 1];
            uint4 o;
            o.x = bf16x2_f32(v0.x, v0.y);
            o.y = bf16x2_f32(v0.z, v0.w);
            o.z = bf16x2_f32(v1.x, v1.y);
            o.w = bf16x2_f32(v1.z, v1.w);
            wb[j] = o;
        }
    }
}

// ---------------------------------------------------------------------------
// Kernel 2: GEMM with fragment software-pipelining:
// B fragments double-buffered across k-steps; A fragments rotated in place
// (reload a[mf] for ks+1 right after its last mma of ks).
// ---------------------------------------------------------------------------
__device__ __forceinline__ void load_chunk(uint32_t st, const __nv_bfloat16* A,
                                           const __nv_bfloat16* W,
                                           int m0, int n0, int k0, int tid) {
#pragma unroll
    for (int t = 0; t < 4; t++) {
        int u = tid + t * THREADS;
        int row = u >> 3, c = u & 7;
        cp16(st + (uint32_t)(row * RS + c * 16),
             A + (size_t)(m0 + row) * KDIM + (size_t)(k0 + c * 8));
    }
#pragma unroll
    for (int t = 0; t < 4; t++) {
        int u = tid + t * THREADS;
        int row = u >> 3, c = u & 7;
        cp16(st + STAGE_A_BYTES + (uint32_t)(row * RS + c * 16),
             W + (size_t)(n0 + row) * KDIM + (size_t)(k0 + c * 8));
    }
}

__global__ void __launch_bounds__(THREADS, 2) gemm_kernel(
    const __nv_bfloat16* __restrict__ A,
    const __nv_bfloat16* __restrict__ W,
    const float* __restrict__ bias,
    float* __restrict__ out) {
    extern __shared__ __align__(128) char smem_raw[];
    const uint32_t sbase = smem_u32(smem_raw);

    const int tid = threadIdx.x;
    const int wid = tid >> 5, lane = tid & 31;
    const int wm = wid >> 2;
    const int wn = wid & 3;
    const int n0 = (int)(blockIdx.x & 15) * TN;
    const int m0 = (int)(blockIdx.x >> 4) * TM;

    const int lrow = lane & 15;
    const int lhalf = lane >> 4;
    const uint32_t abase = (uint32_t)((wm * 64 + lrow) * RS + lhalf * 16);
    const uint32_t bbase = (uint32_t)((wn * 32 + lrow) * RS + lhalf * 16);

    float acc[4][4][4];
#pragma unroll
    for (int i = 0; i < 4; i++)
#pragma unroll
        for (int j = 0; j < 4; j++)
#pragma unroll
            for (int e = 0; e < 4; e++) acc[i][j][e] = 0.0f;

    load_chunk(sbase + 0 * STAGE_BYTES, A, W, m0, n0, 0 * KC, tid);
    asm volatile("cp.async.commit_group;" ::: "memory");
    load_chunk(sbase + 1 * STAGE_BYTES, A, W, m0, n0, 1 * KC, tid);
    asm volatile("cp.async.commit_group;" ::: "memory");

    uint32_t a[4][4];        // rotating A fragments (current k-step)
    uint32_t b[2][2][4];     // double-buffered B fragments (ks parity)

    for (int i = 0; i < NCHUNK; i++) {
        if (i < NCHUNK - 1) asm volatile("cp.async.wait_group 1;" ::: "memory");
        else                asm volatile("cp.async.wait_group 0;" ::: "memory");
        __syncthreads();

        const uint32_t stA = sbase + (i % STAGES) * STAGE_BYTES;
        const uint32_t stB = stA + STAGE_A_BYTES;

        // Prefetch ks=0 fragments before the cp.async issue burst.
#pragma unroll
        for (int nt = 0; nt < 2; nt++)
            ldsm4(b[0][nt], stB + bbase + (uint32_t)(nt * 16 * RS));
#pragma unroll
        for (int mf = 0; mf < 4; mf++)
            ldsm4(a[mf], stA + abase + (uint32_t)(mf * 16 * RS));

        if (i + 2 < NCHUNK) {
            load_chunk(sbase + ((i + 2) % STAGES) * STAGE_BYTES, A, W,
                       m0, n0, (i + 2) * KC, tid);
            asm volatile("cp.async.commit_group;" ::: "memory");
        }

#pragma unroll
        for (int ks = 0; ks < 4; ks++) {
            const int cur = ks & 1, nxt = cur ^ 1;
            // Prefetch next k-step's B early (used after all 16 mmas below).
            if (ks < 3) {
                uint32_t xoff = (uint32_t)((ks + 1) * 32);
#pragma unroll
                for (int nt = 0; nt < 2; nt++)
                    ldsm4(b[nxt][nt], stB + bbase + (uint32_t)(nt * 16 * RS) + xoff);
            }
#pragma unroll
            for (int mf = 0; mf < 4; mf++) {
                mma16816(acc[mf][0], a[mf], b[cur][0][0], b[cur][0][2]);
                mma16816(acc[mf][1], a[mf], b[cur][0][1], b[cur][0][3]);
                mma16816(acc[mf][2], a[mf], b[cur][1][0], b[cur][1][2]);
                mma16816(acc[mf][3], a[mf], b[cur][1][1], b[cur][1][3]);
                // a[mf] dead for this k-step -> rotate in next k-step's frag.
                // 12+ mmas (~96 tensor-cyc) of cover before first use at ks+1.
                if (ks < 3)
                    ldsm4(a[mf], stA + abase +
                          (uint32_t)(mf * 16 * RS + (ks + 1) * 32));
            }
        }
    }

    const int qrow = lane >> 2;
    const int qcol = (lane & 3) * 2;
#pragma unroll
    for (int mf = 0; mf < 4; mf++) {
#pragma unroll
        for (int nf = 0; nf < 4; nf++) {
            int col = n0 + wn * 32 + nf * 8 + qcol;
            __nv_bfloat16 b0 = __float2bfloat16(bias[col]);
            __nv_bfloat16 b1 = __float2bfloat16(bias[col + 1]);
            size_t r0 = (size_t)(m0 + wm * 64 + mf * 16 + qrow);
            float2 v0 = make_float2(
                __bfloat162float(__hadd(__float2bfloat16(acc[mf][nf][0]), b0)),
                __bfloat162float(__hadd(__float2bfloat16(acc[mf][nf][1]), b1)));
            float2 v1 = make_float2(
                __bfloat162float(__hadd(__float2bfloat16(acc[mf][nf][2]), b0)),
                __bfloat162float(__hadd(__float2bfloat16(acc[mf][nf][3]), b1)));
            *reinterpret_cast<float2*>(out + r0 * ODIM + col) = v0;
            *reinterpret_cast<float2*>(out + (r0 + 8) * ODIM + col) = v1;
        }
    }
}

// ---------------------------------------------------------------------------
// kernel_launch — inputs identified BY SIZE; all buffers FLOAT32
// ---------------------------------------------------------------------------
extern "C" void kernel_launch(void* const* d_in, const int* in_sizes, int n_in,
                              void* d_out, int out_size) {
    const float* x    = nullptr;
    const float* w    = nullptr;
    const float* bias = nullptr;
    const float* scale = nullptr;
    for (int i = 0; i < n_in; i++) {
        long s = (long)in_sizes[i];
        if (s == (long)NROWS * KDIM)      x     = (const float*)d_in[i];
        else if (s == (long)ODIM * KDIM)  w     = (const float*)d_in[i];
        else if (s == (long)ODIM)         bias  = (const float*)d_in[i];
        else if (s == 1)                  scale = (const float*)d_in[i];
    }
    float* out = (float*)d_out;

    void* xq_ptr = nullptr;
    void* wb_ptr = nullptr;
    cudaGetSymbolAddress(&xq_ptr, g_xq);
    cudaGetSymbolAddress(&wb_ptr, g_wb);

    prep_kernel<<<4096, 256>>>((const float4*)x, (const float4*)w, scale,
                               (uint4*)xq_ptr, (uint4*)wb_ptr);

    cudaFuncSetAttribute(gemm_kernel, cudaFuncAttributeMaxDynamicSharedMemorySize,
                         SMEM_DYN);
    gemm_kernel<<<(NROWS / TM) * (ODIM / TN), THREADS, SMEM_DYN>>>(
        (const __nv_bfloat16*)xq_ptr, (const __nv_bfloat16*)wb_ptr, bias, out);
}